// round 5
// baseline (speedup 1.0000x reference)
#include <cuda_runtime.h>

#define BB    16
#define NN    512
#define DDIM  16
#define KNN   20
#define CC    30
#define FF    50
#define NCLS  40
#define NT    256      // threads per block
#define WPB   8        // warps per block
#define QPW   4        // queries per warp (processed as 2 interleaved pairs)
#define BPB   16       // blocks per batch (grid.x)
#define STRIDE 20      // floats per tile row (80B: conflict-free for LDS.128, phase-wise)
#define LST   (WPB * 32)   // list slot stride in u64 (lane-major, conflict-free)
#define FULLM 0xFFFFFFFFu

// Scratch (device globals — no allocation allowed)
__device__ float g_feat[BB * NN * DDIM];
__device__ float g_pooled[BB * NN];

extern __shared__ char smem_raw[];

__device__ __forceinline__ unsigned forder(float f) {
    unsigned u = __float_as_uint(f);
    return u ^ (((unsigned)((int)u >> 31)) | 0x80000000u);
}

// in-register bitonic sort of 16 u64 keys, ascending
__device__ __forceinline__ void sort16(unsigned long long* keys) {
    #pragma unroll
    for (int k = 2; k <= 16; k <<= 1) {
        #pragma unroll
        for (int j = k >> 1; j > 0; j >>= 1) {
            #pragma unroll
            for (int i = 0; i < 16; i++) {
                int l = i ^ j;
                if (l > i) {
                    bool up = ((i & k) == 0);
                    unsigned long long a = keys[i], b = keys[l];
                    bool sw = up ? (a > b) : (a < b);
                    keys[i] = sw ? b : a;
                    keys[l] = sw ? a : b;
                }
            }
        }
    }
}

// distances of this lane's 16 candidates to query n -> packed keys
__device__ __forceinline__ void dist16(
    const float* __restrict__ tile, const float* __restrict__ sqc,
    int n, int lane, unsigned long long* keys)
{
    const float4* qr = (const float4*)(tile + n * STRIDE);
    float4 q0 = qr[0], q1 = qr[1], q2 = qr[2], q3 = qr[3];
    float sqn = q0.x * q0.x;
    sqn = fmaf(q0.y, q0.y, sqn); sqn = fmaf(q0.z, q0.z, sqn); sqn = fmaf(q0.w, q0.w, sqn);
    sqn = fmaf(q1.x, q1.x, sqn); sqn = fmaf(q1.y, q1.y, sqn); sqn = fmaf(q1.z, q1.z, sqn); sqn = fmaf(q1.w, q1.w, sqn);
    sqn = fmaf(q2.x, q2.x, sqn); sqn = fmaf(q2.y, q2.y, sqn); sqn = fmaf(q2.z, q2.z, sqn); sqn = fmaf(q2.w, q2.w, sqn);
    sqn = fmaf(q3.x, q3.x, sqn); sqn = fmaf(q3.y, q3.y, sqn); sqn = fmaf(q3.z, q3.z, sqn); sqn = fmaf(q3.w, q3.w, sqn);

    #pragma unroll
    for (int i = 0; i < 16; i++) {
        int j = lane + 32 * i;
        const float4* rr = (const float4*)(tile + j * STRIDE);
        float4 r0 = rr[0], r1 = rr[1], r2 = rr[2], r3 = rr[3];
        float dot = q0.x * r0.x;
        dot = fmaf(q0.y, r0.y, dot); dot = fmaf(q0.z, r0.z, dot); dot = fmaf(q0.w, r0.w, dot);
        dot = fmaf(q1.x, r1.x, dot); dot = fmaf(q1.y, r1.y, dot); dot = fmaf(q1.z, r1.z, dot); dot = fmaf(q1.w, r1.w, dot);
        dot = fmaf(q2.x, r2.x, dot); dot = fmaf(q2.y, r2.y, dot); dot = fmaf(q2.z, r2.z, dot); dot = fmaf(q2.w, r2.w, dot);
        dot = fmaf(q3.x, r3.x, dot); dot = fmaf(q3.y, r3.y, dot); dot = fmaf(q3.z, r3.z, dot); dot = fmaf(q3.w, r3.w, dot);
        float dist = fmaf(-2.f, dot, sqn + sqc[i]);
        keys[i] = ((unsigned long long)forder(dist) << 32) | (unsigned)j;
    }
}

struct TQ { unsigned hi0, lo0, hi1, lo1; int ptr; unsigned sel; };

__device__ __forceinline__ void tq_init(TQ& s, const unsigned long long* keys) {
    s.hi0 = (unsigned)(keys[0] >> 32); s.lo0 = (unsigned)keys[0];
    s.hi1 = (unsigned)(keys[1] >> 32); s.lo1 = (unsigned)keys[1];
    s.ptr = 0; s.sel = 0;
}

// one double-pop round: emits ranks 2r and 2r+1 into lanes 2r / 2r+1
__device__ __forceinline__ void tq_round(
    TQ& s, const unsigned long long* lane_list, int r, int lane)
{
    unsigned mhi1 = __reduce_min_sync(FULLM, s.hi0);
    unsigned c1   = (s.hi0 == mhi1) ? s.lo0 : FULLM;
    unsigned mlo1 = __reduce_min_sync(FULLM, c1);
    bool win1 = (s.hi0 == mhi1) && (s.lo0 == mlo1);
    unsigned chi = win1 ? s.hi1 : s.hi0;
    unsigned clo = win1 ? s.lo1 : s.lo0;
    unsigned mhi2 = __reduce_min_sync(FULLM, chi);
    unsigned c2   = (chi == mhi2) ? clo : FULLM;
    unsigned mlo2 = __reduce_min_sync(FULLM, c2);
    bool win2 = (chi == mhi2) && (clo == mlo2);
    if (lane == 2 * r)     s.sel = mlo1;
    if (lane == 2 * r + 1) s.sel = mlo2;
    int adv = (win1 ? 1 : 0) + (win2 ? 1 : 0);
    if (adv) {
        s.ptr += adv;
        unsigned long long v0 = (s.ptr     < 16) ? lane_list[s.ptr * LST]       : ~0ull;
        unsigned long long v1 = (s.ptr + 1 < 16) ? lane_list[(s.ptr + 1) * LST] : ~0ull;
        s.hi0 = (unsigned)(v0 >> 32); s.lo0 = (unsigned)v0;
        s.hi1 = (unsigned)(v1 >> 32); s.lo1 = (unsigned)v1;
    }
}

// ---------------------------------------------------------------------------
// Stage 1: KNN on raw points + weighted Frechet mean.
// ---------------------------------------------------------------------------
__global__ void __launch_bounds__(NT, 2) stage1_kernel(
    const float* __restrict__ x, const float* __restrict__ w_fm1)
{
    float* tile = (float*)smem_raw;                                 // [512][20]
    unsigned long long* lists = (unsigned long long*)(tile + NN * STRIDE); // [2][16][256]
    float* wc = (float*)(lists + 2 * 16 * LST);                     // [20]

    const int tid = threadIdx.x, lane = tid & 31, warp = tid >> 5;
    const int b = blockIdx.y;

    const float4* x4 = (const float4*)(x + (size_t)b * NN * DDIM);
    #pragma unroll
    for (int i = tid; i < NN * DDIM / 4; i += NT) {
        int row = i >> 2, part = i & 3;
        *(float4*)(tile + row * STRIDE + part * 4) = x4[i];
    }
    if (tid == 0) {
        float mx = -1e30f;
        for (int k = 0; k < KNN; k++) mx = fmaxf(mx, w_fm1[k]);
        float e[KNN], s = 0.f;
        for (int k = 0; k < KNN; k++) { e[k] = expf(w_fm1[k] - mx); s += e[k]; }
        float inv = 1.f / s;
        for (int k = 0; k < KNN; k++) wc[k] = e[k] * inv;
    }
    __syncthreads();

    // per-lane candidate norms (fixed candidate set: lane + 32*i)
    float sqc[16];
    #pragma unroll
    for (int i = 0; i < 16; i++) {
        const float* row = tile + (lane + 32 * i) * STRIDE;
        float s = 0.f;
        #pragma unroll
        for (int d = 0; d < DDIM; d++) s = fmaf(row[d], row[d], s);
        sqc[i] = s;
    }

    unsigned long long* listA = lists + warp * 32 + lane;
    unsigned long long* listB = listA + 16 * LST;
    const int qbase = blockIdx.x * (WPB * QPW) + warp * QPW;

    #pragma unroll 1
    for (int p = 0; p < QPW / 2; p++) {
        const int n0 = qbase + 2 * p, n1 = n0 + 1;
        unsigned long long keysA[16], keysB[16];
        dist16(tile, sqc, n0, lane, keysA);
        sort16(keysA);
        #pragma unroll
        for (int i = 0; i < 16; i++) listA[i * LST] = keysA[i];
        dist16(tile, sqc, n1, lane, keysB);
        sort16(keysB);
        #pragma unroll
        for (int i = 0; i < 16; i++) listB[i * LST] = keysB[i];

        TQ A, Bq;
        tq_init(A, keysA); tq_init(Bq, keysB);
        #pragma unroll
        for (int r = 0; r < KNN / 2; r++) {
            tq_round(A, listA, r, lane);
            tq_round(Bq, listB, r, lane);
        }

        // weighted mean epilogue for both queries
        float acc0 = 0.f, acc1 = 0.f;
        #pragma unroll
        for (int k = 0; k < KNN; k++) {
            unsigned i0 = __shfl_sync(FULLM, A.sel, k);
            unsigned i1 = __shfl_sync(FULLM, Bq.sel, k);
            float w = wc[k];
            acc0 = fmaf(w, tile[i0 * STRIDE + (lane & 15)], acc0);
            acc1 = fmaf(w, tile[i1 * STRIDE + (lane & 15)], acc1);
        }
        if (lane < DDIM) {
            g_feat[((size_t)b * NN + n0) * DDIM + lane] = acc0;
            g_feat[((size_t)b * NN + n1) * DDIM + lane] = acc1;
        }
    }
}

// ---------------------------------------------------------------------------
// Stage 2: KNN on g (same ordering as KNN on the rank-1 lifted features),
// fm2[d,f] = sum_k g[nn_k,d]*A[k,f],  A = sum_c softmax(w_fm2)[c,:]*w_mix1[c]*w_mix2[c,:]
// pooled[n] = mean_f sqrt(sum_d (fm2[d,f]-m_last[d,f])^2 + 1e-8)
// ---------------------------------------------------------------------------
__global__ void __launch_bounds__(NT, 2) stage2_kernel(
    const float* __restrict__ w_fm2, const float* __restrict__ w_mix1,
    const float* __restrict__ w_mix2, const float* __restrict__ m_last)
{
    float* tile = (float*)smem_raw;                                 // [512][20]
    unsigned long long* lists = (unsigned long long*)(tile + NN * STRIDE); // [2][16][256]
    float* A  = (float*)(lists + 2 * 16 * LST);                     // [20][50]
    float* ms = A + KNN * FF;                                       // [16][50]
    float* wc2 = (float*)lists;   // [30][20] aliased into lists (used pre-tournament)

    const int tid = threadIdx.x, lane = tid & 31, warp = tid >> 5;
    const int b = blockIdx.y;

    const float4* x4 = (const float4*)(g_feat + (size_t)b * NN * DDIM);
    #pragma unroll
    for (int i = tid; i < NN * DDIM / 4; i += NT) {
        int row = i >> 2, part = i & 3;
        *(float4*)(tile + row * STRIDE + part * 4) = x4[i];
    }
    if (tid < CC) {
        const float* row = w_fm2 + tid * KNN;
        float mx = -1e30f;
        for (int k = 0; k < KNN; k++) mx = fmaxf(mx, row[k]);
        float e[KNN], s = 0.f;
        for (int k = 0; k < KNN; k++) { e[k] = expf(row[k] - mx); s += e[k]; }
        float inv = 1.f / s;
        for (int k = 0; k < KNN; k++) wc2[tid * KNN + k] = e[k] * inv;
    }
    for (int i = tid; i < DDIM * FF; i += NT) ms[i] = m_last[i];
    __syncthreads();
    // A[k][f] = sum_c wc2[c][k] * w_mix1[c] * w_mix2[c][f]
    for (int i = tid; i < KNN * FF; i += NT) {
        int k = i / FF, f = i % FF;
        float acc = 0.f;
        #pragma unroll
        for (int c = 0; c < CC; c++)
            acc = fmaf(wc2[c * KNN + k] * __ldg(w_mix1 + c), __ldg(w_mix2 + c * FF + f), acc);
        A[i] = acc;
    }
    __syncthreads();   // lists area free after this point

    float sqc[16];
    #pragma unroll
    for (int i = 0; i < 16; i++) {
        const float* row = tile + (lane + 32 * i) * STRIDE;
        float s = 0.f;
        #pragma unroll
        for (int d = 0; d < DDIM; d++) s = fmaf(row[d], row[d], s);
        sqc[i] = s;
    }

    unsigned long long* listA = lists + warp * 32 + lane;
    unsigned long long* listB = listA + 16 * LST;
    const int qbase = blockIdx.x * (WPB * QPW) + warp * QPW;

    const int f0 = lane, f1 = lane + 32;
    const bool v1 = (f1 < FF);

    #pragma unroll 1
    for (int p = 0; p < QPW / 2; p++) {
        const int n0 = qbase + 2 * p, n1 = n0 + 1;
        unsigned long long keysA[16], keysB[16];
        dist16(tile, sqc, n0, lane, keysA);
        sort16(keysA);
        #pragma unroll
        for (int i = 0; i < 16; i++) listA[i * LST] = keysA[i];
        dist16(tile, sqc, n1, lane, keysB);
        sort16(keysB);
        #pragma unroll
        for (int i = 0; i < 16; i++) listB[i * LST] = keysB[i];

        TQ Aq, Bq;
        tq_init(Aq, keysA); tq_init(Bq, keysB);
        #pragma unroll
        for (int r = 0; r < KNN / 2; r++) {
            tq_round(Aq, listA, r, lane);
            tq_round(Bq, listB, r, lane);
        }

        #pragma unroll 1
        for (int qq = 0; qq < 2; qq++) {
            unsigned sel = qq ? Bq.sel : Aq.sel;
            int n = qq ? n1 : n0;
            float acc0[DDIM], acc1[DDIM];
            #pragma unroll
            for (int d = 0; d < DDIM; d++) { acc0[d] = 0.f; acc1[d] = 0.f; }
            #pragma unroll
            for (int k = 0; k < KNN; k++) {
                unsigned idx = __shfl_sync(FULLM, sel, k);
                float a0 = A[k * FF + f0];
                float a1 = v1 ? A[k * FF + f1] : 0.f;
                const float* row = tile + idx * STRIDE;
                #pragma unroll
                for (int d = 0; d < DDIM; d++) {
                    float xv = row[d];                   // LDS broadcast
                    acc0[d] = fmaf(xv, a0, acc0[d]);
                    acc1[d] = fmaf(xv, a1, acc1[d]);
                }
            }
            float s0 = 0.f, s1 = 0.f;
            #pragma unroll
            for (int d = 0; d < DDIM; d++) {
                float d0 = acc0[d] - ms[d * FF + f0];
                s0 = fmaf(d0, d0, s0);
                float d1 = acc1[d] - (v1 ? ms[d * FF + f1] : 0.f);
                s1 = fmaf(d1, d1, s1);
            }
            float per = sqrtf(s0 + 1e-8f) + (v1 ? sqrtf(s1 + 1e-8f) : 0.f);
            #pragma unroll
            for (int off = 16; off; off >>= 1)
                per += __shfl_xor_sync(FULLM, per, off);
            if (lane == 0)
                g_pooled[(size_t)b * NN + n] = per * (1.f / (float)FF);
        }
    }
}

// ---------------------------------------------------------------------------
// Final classifier: out[b][j] = sum_n pooled[b][n]*w_cls[n][j] + b_cls[j]
// ---------------------------------------------------------------------------
__global__ void __launch_bounds__(512) cls_kernel(
    const float* __restrict__ w_cls, const float* __restrict__ b_cls,
    float* __restrict__ out)
{
    __shared__ float ps[NN];
    const int tid = threadIdx.x;
    const int b = blockIdx.x;
    ps[tid] = g_pooled[(size_t)b * NN + tid];
    __syncthreads();
    if (tid < NCLS) {
        float a0 = 0.f, a1 = 0.f, a2 = 0.f, a3 = 0.f;
        #pragma unroll 4
        for (int n = 0; n < NN; n += 4) {
            a0 = fmaf(ps[n + 0], w_cls[(n + 0) * NCLS + tid], a0);
            a1 = fmaf(ps[n + 1], w_cls[(n + 1) * NCLS + tid], a1);
            a2 = fmaf(ps[n + 2], w_cls[(n + 2) * NCLS + tid], a2);
            a3 = fmaf(ps[n + 3], w_cls[(n + 3) * NCLS + tid], a3);
        }
        out[b * NCLS + tid] = (a0 + a1) + (a2 + a3) + b_cls[tid];
    }
}

extern "C" void kernel_launch(void* const* d_in, const int* in_sizes, int n_in,
                              void* d_out, int out_size)
{
    const float* x      = (const float*)d_in[0];  // [16,512,16,1]
    const float* w_fm1  = (const float*)d_in[1];  // [1,20]
    const float* w_mix1 = (const float*)d_in[2];  // [1,30]
    const float* w_fm2  = (const float*)d_in[3];  // [30,20]
    const float* w_mix2 = (const float*)d_in[4];  // [30,50]
    const float* m_last = (const float*)d_in[5];  // [16,50]
    const float* w_cls  = (const float*)d_in[6];  // [512,40]
    const float* b_cls  = (const float*)d_in[7];  // [40]
    float* out = (float*)d_out;                   // [16,40]

    constexpr size_t LISTB   = 2ull * 16 * LST * 8;                       // 65536
    constexpr size_t S1_SMEM = (size_t)NN * STRIDE * 4 + LISTB + KNN * 4;
    constexpr size_t S2_SMEM = (size_t)NN * STRIDE * 4 + LISTB
                             + (KNN * FF + DDIM * FF) * 4;

    cudaFuncSetAttribute(stage1_kernel, cudaFuncAttributeMaxDynamicSharedMemorySize, (int)S1_SMEM);
    cudaFuncSetAttribute(stage2_kernel, cudaFuncAttributeMaxDynamicSharedMemorySize, (int)S2_SMEM);

    dim3 grid(BPB, BB);
    stage1_kernel<<<grid, NT, S1_SMEM>>>(x, w_fm1);
    stage2_kernel<<<grid, NT, S2_SMEM>>>(w_fm2, w_mix1, w_mix2, m_last);
    cls_kernel<<<BB, 512>>>(w_cls, b_cls, out);
}

// round 6
// speedup vs baseline: 1.1621x; 1.1621x over previous
#include <cuda_runtime.h>

#define BB    16
#define NN    512
#define DDIM  16
#define KNN   20
#define CC    30
#define FF    50
#define NCLS  40
#define NT    128      // threads per block (4 warps)
#define WPB   4
#define QPW   4        // queries per warp
#define BPB   32       // blocks per batch (grid.x)
#define STRIDE 20      // floats per tile row (80B, 16B-aligned, conflict-free)
#define FULLM 0xFFFFFFFFu

// Scratch (device globals — no allocation allowed)
__device__ float g_feat[BB * NN * DDIM];
__device__ float g_pooled[BB * NN];

extern __shared__ char smem_raw[];

__device__ __forceinline__ unsigned forder(float f) {
    unsigned u = __float_as_uint(f);
    return u ^ (((unsigned)((int)u >> 31)) | 0x80000000u);
}

// in-register bitonic sort of 16 u64 keys, ascending
__device__ __forceinline__ void sort16(unsigned long long* keys) {
    #pragma unroll
    for (int k = 2; k <= 16; k <<= 1) {
        #pragma unroll
        for (int j = k >> 1; j > 0; j >>= 1) {
            #pragma unroll
            for (int i = 0; i < 16; i++) {
                int l = i ^ j;
                if (l > i) {
                    bool up = ((i & k) == 0);
                    unsigned long long a = keys[i], b = keys[l];
                    bool sw = up ? (a > b) : (a < b);
                    keys[i] = sw ? b : a;
                    keys[l] = sw ? a : b;
                }
            }
        }
    }
}

// distances of this lane's 16 candidates (j = lane+32i) to query n -> packed keys
__device__ __forceinline__ void dist16(
    const float* __restrict__ tile, const float* __restrict__ sq,
    int n, int lane, unsigned long long* keys)
{
    const float4* qr = (const float4*)(tile + n * STRIDE);
    float4 q0 = qr[0], q1 = qr[1], q2 = qr[2], q3 = qr[3];
    float sqn = sq[n];
    #pragma unroll
    for (int i = 0; i < 16; i++) {
        int j = lane + 32 * i;
        const float4* rr = (const float4*)(tile + j * STRIDE);
        float4 r0 = rr[0], r1 = rr[1], r2 = rr[2], r3 = rr[3];
        float dot = q0.x * r0.x;
        dot = fmaf(q0.y, r0.y, dot); dot = fmaf(q0.z, r0.z, dot); dot = fmaf(q0.w, r0.w, dot);
        dot = fmaf(q1.x, r1.x, dot); dot = fmaf(q1.y, r1.y, dot); dot = fmaf(q1.z, r1.z, dot); dot = fmaf(q1.w, r1.w, dot);
        dot = fmaf(q2.x, r2.x, dot); dot = fmaf(q2.y, r2.y, dot); dot = fmaf(q2.z, r2.z, dot); dot = fmaf(q2.w, r2.w, dot);
        dot = fmaf(q3.x, r3.x, dot); dot = fmaf(q3.y, r3.y, dot); dot = fmaf(q3.z, r3.z, dot); dot = fmaf(q3.w, r3.w, dot);
        float dist = fmaf(-2.f, dot, sqn + sq[j]);
        keys[i] = ((unsigned long long)forder(dist) << 32) | (unsigned)j;
    }
}

// Exact ranked top-20: 10 double-pop rounds, register shift-list (no SMEM, no reload).
// Lane r (r<20) ends holding the index of the r-th nearest neighbor.
__device__ __forceinline__ unsigned topk20(unsigned long long* keys, int lane)
{
    unsigned sel = 0;
    #pragma unroll
    for (int r = 0; r < KNN / 2; r++) {
        unsigned hi0 = (unsigned)(keys[0] >> 32), lo0 = (unsigned)keys[0];
        unsigned hi1 = (unsigned)(keys[1] >> 32), lo1 = (unsigned)keys[1];
        unsigned mhi1 = __reduce_min_sync(FULLM, hi0);
        unsigned c1   = (hi0 == mhi1) ? lo0 : FULLM;
        unsigned mlo1 = __reduce_min_sync(FULLM, c1);
        bool win1 = (hi0 == mhi1) && (lo0 == mlo1);
        unsigned chi = win1 ? hi1 : hi0, clo = win1 ? lo1 : lo0;
        unsigned mhi2 = __reduce_min_sync(FULLM, chi);
        unsigned c2   = (chi == mhi2) ? clo : FULLM;
        unsigned mlo2 = __reduce_min_sync(FULLM, c2);
        bool win2 = (chi == mhi2) && (clo == mlo2);
        if (lane == 2 * r)     sel = mlo1;
        if (lane == 2 * r + 1) sel = mlo2;
        int adv = (int)win1 + (int)win2;
        if (adv) {
            #pragma unroll
            for (int i = 0; i < 15; i++) keys[i] = keys[i + 1];
            keys[15] = ~0ull;
            if (adv == 2) {
                #pragma unroll
                for (int i = 0; i < 15; i++) keys[i] = keys[i + 1];
                keys[15] = ~0ull;
            }
        }
    }
    return sel;
}

// ---------------------------------------------------------------------------
// Stage 1: KNN on raw points + weighted Frechet mean.
// ---------------------------------------------------------------------------
__global__ void __launch_bounds__(NT, 5) stage1_kernel(
    const float* __restrict__ x, const float* __restrict__ w_fm1)
{
    float* tile = (float*)smem_raw;                // [512][20]
    float* sq   = tile + NN * STRIDE;              // [512]
    float* wc   = sq + NN;                         // [20]

    const int tid = threadIdx.x, lane = tid & 31, warp = tid >> 5;
    const int b = blockIdx.y;

    const float4* x4 = (const float4*)(x + (size_t)b * NN * DDIM);
    #pragma unroll
    for (int i = tid; i < NN * DDIM / 4; i += NT) {
        int row = i >> 2, part = i & 3;
        *(float4*)(tile + row * STRIDE + part * 4) = x4[i];
    }
    if (tid == 0) {
        float mx = -1e30f;
        for (int k = 0; k < KNN; k++) mx = fmaxf(mx, w_fm1[k]);
        float e[KNN], s = 0.f;
        for (int k = 0; k < KNN; k++) { e[k] = expf(w_fm1[k] - mx); s += e[k]; }
        float inv = 1.f / s;
        for (int k = 0; k < KNN; k++) wc[k] = e[k] * inv;
    }
    __syncthreads();
    for (int r = tid; r < NN; r += NT) {
        float s = 0.f;
        #pragma unroll
        for (int d = 0; d < DDIM; d++) { float v = tile[r * STRIDE + d]; s = fmaf(v, v, s); }
        sq[r] = s;
    }
    __syncthreads();

    const int qbase = blockIdx.x * (WPB * QPW) + warp * QPW;
    #pragma unroll 1
    for (int t = 0; t < QPW; t++) {
        int n = qbase + t;
        unsigned long long keys[16];
        dist16(tile, sq, n, lane, keys);
        sort16(keys);
        unsigned sel = topk20(keys, lane);

        float acc = 0.f;
        #pragma unroll
        for (int k = 0; k < KNN; k++) {
            unsigned idx = __shfl_sync(FULLM, sel, k);
            acc = fmaf(wc[k], tile[idx * STRIDE + (lane & 15)], acc);
        }
        if (lane < DDIM)
            g_feat[((size_t)b * NN + n) * DDIM + lane] = acc;
    }
}

// ---------------------------------------------------------------------------
// Stage 2: KNN on g (same ordering as KNN on the rank-1 lifted features),
// fm2[d,f] = sum_k g[nn_k,d]*A[k,f],  A = sum_c softmax(w_fm2)[c,:]*w_mix1[c]*w_mix2[c,:]
// pooled[n] = mean_f sqrt(sum_d (fm2[d,f]-m_last[d,f])^2 + 1e-8)
// ---------------------------------------------------------------------------
__global__ void __launch_bounds__(NT, 4) stage2_kernel(
    const float* __restrict__ w_fm2, const float* __restrict__ w_mix1,
    const float* __restrict__ w_mix2, const float* __restrict__ m_last)
{
    float* tile = (float*)smem_raw;                // [512][20]
    float* sq   = tile + NN * STRIDE;              // [512]
    float* A    = sq + NN;                         // [20][50]
    float* ms   = A + KNN * FF;                    // [16][50]
    float* wc2  = ms + DDIM * FF;                  // [30][20]

    const int tid = threadIdx.x, lane = tid & 31, warp = tid >> 5;
    const int b = blockIdx.y;

    const float4* x4 = (const float4*)(g_feat + (size_t)b * NN * DDIM);
    #pragma unroll
    for (int i = tid; i < NN * DDIM / 4; i += NT) {
        int row = i >> 2, part = i & 3;
        *(float4*)(tile + row * STRIDE + part * 4) = x4[i];
    }
    if (tid < CC) {
        const float* row = w_fm2 + tid * KNN;
        float mx = -1e30f;
        for (int k = 0; k < KNN; k++) mx = fmaxf(mx, row[k]);
        float e[KNN], s = 0.f;
        for (int k = 0; k < KNN; k++) { e[k] = expf(row[k] - mx); s += e[k]; }
        float inv = 1.f / s;
        for (int k = 0; k < KNN; k++) wc2[tid * KNN + k] = e[k] * inv;
    }
    for (int i = tid; i < DDIM * FF; i += NT) ms[i] = m_last[i];
    for (int r = tid; r < NN; r += NT) {
        float s = 0.f;
        #pragma unroll
        for (int d = 0; d < DDIM; d++) { float v = tile[r * STRIDE + d]; s = fmaf(v, v, s); }
        sq[r] = s;
    }
    __syncthreads();
    // A[k][f] = sum_c wc2[c][k] * w_mix1[c] * w_mix2[c][f]
    for (int i = tid; i < KNN * FF; i += NT) {
        int k = i / FF, f = i % FF;
        float acc = 0.f;
        #pragma unroll
        for (int c = 0; c < CC; c++)
            acc = fmaf(wc2[c * KNN + k] * __ldg(w_mix1 + c), __ldg(w_mix2 + c * FF + f), acc);
        A[i] = acc;
    }
    __syncthreads();

    const int qbase = blockIdx.x * (WPB * QPW) + warp * QPW;
    const int f0 = lane, f1 = lane + 32;
    const bool v1 = (f1 < FF);

    #pragma unroll 1
    for (int t = 0; t < QPW; t++) {
        int n = qbase + t;
        unsigned long long keys[16];
        dist16(tile, sq, n, lane, keys);
        sort16(keys);
        unsigned sel = topk20(keys, lane);

        float acc0[DDIM], acc1[DDIM];
        #pragma unroll
        for (int d = 0; d < DDIM; d++) { acc0[d] = 0.f; acc1[d] = 0.f; }
        #pragma unroll
        for (int k = 0; k < KNN; k++) {
            unsigned idx = __shfl_sync(FULLM, sel, k);
            float a0 = A[k * FF + f0];
            float a1 = v1 ? A[k * FF + f1] : 0.f;
            const float4* row = (const float4*)(tile + idx * STRIDE);
            float4 r0 = row[0], r1 = row[1], r2 = row[2], r3 = row[3];
            acc0[ 0] = fmaf(r0.x, a0, acc0[ 0]); acc1[ 0] = fmaf(r0.x, a1, acc1[ 0]);
            acc0[ 1] = fmaf(r0.y, a0, acc0[ 1]); acc1[ 1] = fmaf(r0.y, a1, acc1[ 1]);
            acc0[ 2] = fmaf(r0.z, a0, acc0[ 2]); acc1[ 2] = fmaf(r0.z, a1, acc1[ 2]);
            acc0[ 3] = fmaf(r0.w, a0, acc0[ 3]); acc1[ 3] = fmaf(r0.w, a1, acc1[ 3]);
            acc0[ 4] = fmaf(r1.x, a0, acc0[ 4]); acc1[ 4] = fmaf(r1.x, a1, acc1[ 4]);
            acc0[ 5] = fmaf(r1.y, a0, acc0[ 5]); acc1[ 5] = fmaf(r1.y, a1, acc1[ 5]);
            acc0[ 6] = fmaf(r1.z, a0, acc0[ 6]); acc1[ 6] = fmaf(r1.z, a1, acc1[ 6]);
            acc0[ 7] = fmaf(r1.w, a0, acc0[ 7]); acc1[ 7] = fmaf(r1.w, a1, acc1[ 7]);
            acc0[ 8] = fmaf(r2.x, a0, acc0[ 8]); acc1[ 8] = fmaf(r2.x, a1, acc1[ 8]);
            acc0[ 9] = fmaf(r2.y, a0, acc0[ 9]); acc1[ 9] = fmaf(r2.y, a1, acc1[ 9]);
            acc0[10] = fmaf(r2.z, a0, acc0[10]); acc1[10] = fmaf(r2.z, a1, acc1[10]);
            acc0[11] = fmaf(r2.w, a0, acc0[11]); acc1[11] = fmaf(r2.w, a1, acc1[11]);
            acc0[12] = fmaf(r3.x, a0, acc0[12]); acc1[12] = fmaf(r3.x, a1, acc1[12]);
            acc0[13] = fmaf(r3.y, a0, acc0[13]); acc1[13] = fmaf(r3.y, a1, acc1[13]);
            acc0[14] = fmaf(r3.z, a0, acc0[14]); acc1[14] = fmaf(r3.z, a1, acc1[14]);
            acc0[15] = fmaf(r3.w, a0, acc0[15]); acc1[15] = fmaf(r3.w, a1, acc1[15]);
        }
        float s0 = 0.f, s1 = 0.f;
        #pragma unroll
        for (int d = 0; d < DDIM; d++) {
            float d0 = acc0[d] - ms[d * FF + f0];
            s0 = fmaf(d0, d0, s0);
            float d1 = acc1[d] - (v1 ? ms[d * FF + f1] : 0.f);
            s1 = fmaf(d1, d1, s1);
        }
        float per = sqrtf(s0 + 1e-8f) + (v1 ? sqrtf(s1 + 1e-8f) : 0.f);
        #pragma unroll
        for (int off = 16; off; off >>= 1)
            per += __shfl_xor_sync(FULLM, per, off);
        if (lane == 0)
            g_pooled[(size_t)b * NN + n] = per * (1.f / (float)FF);
    }
}

// ---------------------------------------------------------------------------
// Final classifier: out[b][j] = sum_n pooled[b][n]*w_cls[n][j] + b_cls[j]
// ---------------------------------------------------------------------------
__global__ void __launch_bounds__(512) cls_kernel(
    const float* __restrict__ w_cls, const float* __restrict__ b_cls,
    float* __restrict__ out)
{
    __shared__ float ps[NN];
    const int tid = threadIdx.x;
    const int b = blockIdx.x;
    ps[tid] = g_pooled[(size_t)b * NN + tid];
    __syncthreads();
    if (tid < NCLS) {
        float a0 = 0.f, a1 = 0.f, a2 = 0.f, a3 = 0.f;
        #pragma unroll 4
        for (int n = 0; n < NN; n += 4) {
            a0 = fmaf(ps[n + 0], w_cls[(n + 0) * NCLS + tid], a0);
            a1 = fmaf(ps[n + 1], w_cls[(n + 1) * NCLS + tid], a1);
            a2 = fmaf(ps[n + 2], w_cls[(n + 2) * NCLS + tid], a2);
            a3 = fmaf(ps[n + 3], w_cls[(n + 3) * NCLS + tid], a3);
        }
        out[b * NCLS + tid] = (a0 + a1) + (a2 + a3) + b_cls[tid];
    }
}

extern "C" void kernel_launch(void* const* d_in, const int* in_sizes, int n_in,
                              void* d_out, int out_size)
{
    const float* x      = (const float*)d_in[0];  // [16,512,16,1]
    const float* w_fm1  = (const float*)d_in[1];  // [1,20]
    const float* w_mix1 = (const float*)d_in[2];  // [1,30]
    const float* w_fm2  = (const float*)d_in[3];  // [30,20]
    const float* w_mix2 = (const float*)d_in[4];  // [30,50]
    const float* m_last = (const float*)d_in[5];  // [16,50]
    const float* w_cls  = (const float*)d_in[6];  // [512,40]
    const float* b_cls  = (const float*)d_in[7];  // [40]
    float* out = (float*)d_out;                   // [16,40]

    constexpr size_t S1_SMEM = ((size_t)NN * STRIDE + NN + KNN) * 4;                 // 43088
    constexpr size_t S2_SMEM = ((size_t)NN * STRIDE + NN + KNN * FF + DDIM * FF
                               + CC * KNN) * 4;                                      // 52608

    cudaFuncSetAttribute(stage1_kernel, cudaFuncAttributeMaxDynamicSharedMemorySize, (int)S1_SMEM);
    cudaFuncSetAttribute(stage2_kernel, cudaFuncAttributeMaxDynamicSharedMemorySize, (int)S2_SMEM);

    dim3 grid(BPB, BB);
    stage1_kernel<<<grid, NT, S1_SMEM>>>(x, w_fm1);
    stage2_kernel<<<grid, NT, S2_SMEM>>>(w_fm2, w_mix1, w_mix2, m_last);
    cls_kernel<<<BB, 512>>>(w_cls, b_cls, out);
}

// round 8
// speedup vs baseline: 1.6029x; 1.3793x over previous
#include <cuda_runtime.h>

#define BB    16
#define NN    512
#define DDIM  16
#define KNN   20
#define CC    30
#define FF    50
#define NCLS  40
#define NT    256      // threads per block (8 warps)
#define WPB   8
#define BPB   64       // blocks per batch (grid.x); 1 query per warp
#define STRIDE 20      // floats per tile row: 16 coords + sq at [16] (conflict-free)
#define FULLM 0xFFFFFFFFu

// Scratch (device globals — no allocation allowed)
__device__ float g_feat[BB * NN * DDIM];
__device__ float g_pooled[BB * NN];

extern __shared__ char smem_raw[];

__device__ __forceinline__ unsigned forder(float f) {
    unsigned u = __float_as_uint(f);
    return u ^ (((unsigned)((int)u >> 31)) | 0x80000000u);
}

// in-register bitonic sort of 16 u64 keys, ascending
__device__ __forceinline__ void sort16(unsigned long long* keys) {
    #pragma unroll
    for (int k = 2; k <= 16; k <<= 1) {
        #pragma unroll
        for (int j = k >> 1; j > 0; j >>= 1) {
            #pragma unroll
            for (int i = 0; i < 16; i++) {
                int l = i ^ j;
                if (l > i) {
                    bool up = ((i & k) == 0);
                    unsigned long long a = keys[i], b = keys[l];
                    bool sw = up ? (a > b) : (a < b);
                    keys[i] = sw ? b : a;
                    keys[l] = sw ? a : b;
                }
            }
        }
    }
}

// distances (shifted by -sq[n]: same ordering) of this lane's 16 candidates
// j = lane+32i to query n -> packed (dist,idx) keys
__device__ __forceinline__ void dist16(
    const float* __restrict__ tile, int n, int lane, unsigned long long* keys)
{
    const float4* qr = (const float4*)(tile + n * STRIDE);
    float4 q0 = qr[0], q1 = qr[1], q2 = qr[2], q3 = qr[3];
    #pragma unroll
    for (int i = 0; i < 16; i++) {
        int j = lane + 32 * i;
        const float* rp = tile + j * STRIDE;
        const float4* rr = (const float4*)rp;
        float4 r0 = rr[0], r1 = rr[1], r2 = rr[2], r3 = rr[3];
        float dot = q0.x * r0.x;
        dot = fmaf(q0.y, r0.y, dot); dot = fmaf(q0.z, r0.z, dot); dot = fmaf(q0.w, r0.w, dot);
        dot = fmaf(q1.x, r1.x, dot); dot = fmaf(q1.y, r1.y, dot); dot = fmaf(q1.z, r1.z, dot); dot = fmaf(q1.w, r1.w, dot);
        dot = fmaf(q2.x, r2.x, dot); dot = fmaf(q2.y, r2.y, dot); dot = fmaf(q2.z, r2.z, dot); dot = fmaf(q2.w, r2.w, dot);
        dot = fmaf(q3.x, r3.x, dot); dot = fmaf(q3.y, r3.y, dot); dot = fmaf(q3.z, r3.z, dot); dot = fmaf(q3.w, r3.w, dot);
        float dist = fmaf(-2.f, dot, rp[16]);   // sq[j] - 2*dot  (order-equivalent)
        keys[i] = ((unsigned long long)forder(dist) << 32) | (unsigned)j;
    }
}

// Exact ranked top-20: 10 double-pop rounds, register shift-list.
// Lane r (r<20) ends holding the index of the r-th nearest neighbor
// (ascending distance; ties -> lowest index == stable jax top_k).
__device__ __forceinline__ unsigned topk20(unsigned long long* keys, int lane)
{
    unsigned sel = 0;
    #pragma unroll
    for (int r = 0; r < KNN / 2; r++) {
        unsigned hi0 = (unsigned)(keys[0] >> 32), lo0 = (unsigned)keys[0];
        unsigned hi1 = (unsigned)(keys[1] >> 32), lo1 = (unsigned)keys[1];
        unsigned mhi1 = __reduce_min_sync(FULLM, hi0);
        unsigned c1   = (hi0 == mhi1) ? lo0 : FULLM;
        unsigned mlo1 = __reduce_min_sync(FULLM, c1);
        bool win1 = (hi0 == mhi1) && (lo0 == mlo1);
        unsigned chi = win1 ? hi1 : hi0, clo = win1 ? lo1 : lo0;
        unsigned mhi2 = __reduce_min_sync(FULLM, chi);
        unsigned c2   = (chi == mhi2) ? clo : FULLM;
        unsigned mlo2 = __reduce_min_sync(FULLM, c2);
        bool win2 = (chi == mhi2) && (clo == mlo2);
        if (lane == 2 * r)     sel = mlo1;
        if (lane == 2 * r + 1) sel = mlo2;
        int adv = (int)win1 + (int)win2;
        if (adv) {
            #pragma unroll
            for (int i = 0; i < 15; i++) keys[i] = keys[i + 1];
            keys[15] = ~0ull;
            if (adv == 2) {
                #pragma unroll
                for (int i = 0; i < 15; i++) keys[i] = keys[i + 1];
                keys[15] = ~0ull;
            }
        }
    }
    return sel;
}

// shared tile setup: load x[b] transposed into [512][20] with sq in column 16
__device__ __forceinline__ void load_tile(float* tile, const float4* x4, int tid)
{
    #pragma unroll
    for (int i = tid; i < NN * DDIM / 4; i += NT) {
        int row = i >> 2, part = i & 3;
        *(float4*)(tile + row * STRIDE + part * 4) = x4[i];
    }
    __syncthreads();
    #pragma unroll
    for (int r = tid; r < NN; r += NT) {
        const float* rp = tile + r * STRIDE;
        float s = rp[0] * rp[0];
        #pragma unroll
        for (int d = 1; d < DDIM; d++) s = fmaf(rp[d], rp[d], s);
        tile[r * STRIDE + 16] = s;     // same fma order as dist16 -> self strictly min
    }
}

// ---------------------------------------------------------------------------
// Stage 1: KNN on raw points + weighted Frechet mean.
// ---------------------------------------------------------------------------
__global__ void __launch_bounds__(NT, 4) stage1_kernel(
    const float* __restrict__ x, const float* __restrict__ w_fm1)
{
    float* tile = (float*)smem_raw;                // [512][20]
    float* wc   = tile + NN * STRIDE;              // [20]

    const int tid = threadIdx.x, lane = tid & 31, warp = tid >> 5;
    const int b = blockIdx.y;

    load_tile(tile, (const float4*)(x + (size_t)b * NN * DDIM), tid);
    if (tid == 0) {
        float mx = -1e30f;
        for (int k = 0; k < KNN; k++) mx = fmaxf(mx, w_fm1[k]);
        float e[KNN], s = 0.f;
        for (int k = 0; k < KNN; k++) { e[k] = expf(w_fm1[k] - mx); s += e[k]; }
        float inv = 1.f / s;
        for (int k = 0; k < KNN; k++) wc[k] = e[k] * inv;
    }
    __syncthreads();

    const int n = blockIdx.x * WPB + warp;         // 1 query per warp
    unsigned long long keys[16];
    dist16(tile, n, lane, keys);
    sort16(keys);
    unsigned sel = topk20(keys, lane);

    float acc = 0.f;
    #pragma unroll
    for (int k = 0; k < KNN; k++) {
        unsigned idx = __shfl_sync(FULLM, sel, k);
        acc = fmaf(wc[k], tile[idx * STRIDE + (lane & 15)], acc);
    }
    if (lane < DDIM)
        g_feat[((size_t)b * NN + n) * DDIM + lane] = acc;
}

// ---------------------------------------------------------------------------
// Stage 2: KNN on g (same ordering as KNN on the rank-1 lifted features),
// fm2[d,f] = sum_k g[nn_k,d]*A[k,f],  A = sum_c softmax(w_fm2)[c,:]*w_mix1[c]*w_mix2[c,:]
// pooled[n] = mean_f sqrt(sum_d (fm2[d,f]-m_last[d,f])^2 + 1e-8)
// ---------------------------------------------------------------------------
__global__ void __launch_bounds__(NT, 4) stage2_kernel(
    const float* __restrict__ w_fm2, const float* __restrict__ w_mix1,
    const float* __restrict__ w_mix2, const float* __restrict__ m_last)
{
    float* tile = (float*)smem_raw;                // [512][20]
    float* A    = tile + NN * STRIDE;              // [20][50]
    float* ms   = A + KNN * FF;                    // [16][50]
    float* wc2  = ms + DDIM * FF;                  // [30][20]

    const int tid = threadIdx.x, lane = tid & 31, warp = tid >> 5;
    const int b = blockIdx.y;

    load_tile(tile, (const float4*)(g_feat + (size_t)b * NN * DDIM), tid);
    if (tid < CC) {
        const float* row = w_fm2 + tid * KNN;
        float mx = -1e30f;
        for (int k = 0; k < KNN; k++) mx = fmaxf(mx, row[k]);
        float e[KNN], s = 0.f;
        for (int k = 0; k < KNN; k++) { e[k] = expf(row[k] - mx); s += e[k]; }
        float inv = 1.f / s;
        for (int k = 0; k < KNN; k++) wc2[tid * KNN + k] = e[k] * inv;
    }
    for (int i = tid; i < DDIM * FF; i += NT) ms[i] = m_last[i];
    __syncthreads();
    // A[k][f] = sum_c wc2[c][k] * w_mix1[c] * w_mix2[c][f]
    for (int i = tid; i < KNN * FF; i += NT) {
        int k = i / FF, f = i % FF;
        float acc = 0.f;
        #pragma unroll
        for (int c = 0; c < CC; c++)
            acc = fmaf(wc2[c * KNN + k] * __ldg(w_mix1 + c), __ldg(w_mix2 + c * FF + f), acc);
        A[i] = acc;
    }
    __syncthreads();

    const int n = blockIdx.x * WPB + warp;
    unsigned long long keys[16];
    dist16(tile, n, lane, keys);
    sort16(keys);
    unsigned sel = topk20(keys, lane);

    const int f0 = lane, f1 = lane + 32;
    const bool v1 = (f1 < FF);
    float acc0[DDIM], acc1[DDIM];
    #pragma unroll
    for (int d = 0; d < DDIM; d++) { acc0[d] = 0.f; acc1[d] = 0.f; }
    #pragma unroll
    for (int k = 0; k < KNN; k++) {
        unsigned idx = __shfl_sync(FULLM, sel, k);
        float a0 = A[k * FF + f0];
        float a1 = v1 ? A[k * FF + f1] : 0.f;
        const float4* row = (const float4*)(tile + idx * STRIDE);
        float4 r0 = row[0], r1 = row[1], r2 = row[2], r3 = row[3];
        acc0[ 0] = fmaf(r0.x, a0, acc0[ 0]); acc1[ 0] = fmaf(r0.x, a1, acc1[ 0]);
        acc0[ 1] = fmaf(r0.y, a0, acc0[ 1]); acc1[ 1] = fmaf(r0.y, a1, acc1[ 1]);
        acc0[ 2] = fmaf(r0.z, a0, acc0[ 2]); acc1[ 2] = fmaf(r0.z, a1, acc1[ 2]);
        acc0[ 3] = fmaf(r0.w, a0, acc0[ 3]); acc1[ 3] = fmaf(r0.w, a1, acc1[ 3]);
        acc0[ 4] = fmaf(r1.x, a0, acc0[ 4]); acc1[ 4] = fmaf(r1.x, a1, acc1[ 4]);
        acc0[ 5] = fmaf(r1.y, a0, acc0[ 5]); acc1[ 5] = fmaf(r1.y, a1, acc1[ 5]);
        acc0[ 6] = fmaf(r1.z, a0, acc0[ 6]); acc1[ 6] = fmaf(r1.z, a1, acc1[ 6]);
        acc0[ 7] = fmaf(r1.w, a0, acc0[ 7]); acc1[ 7] = fmaf(r1.w, a1, acc1[ 7]);
        acc0[ 8] = fmaf(r2.x, a0, acc0[ 8]); acc1[ 8] = fmaf(r2.x, a1, acc1[ 8]);
        acc0[ 9] = fmaf(r2.y, a0, acc0[ 9]); acc1[ 9] = fmaf(r2.y, a1, acc1[ 9]);
        acc0[10] = fmaf(r2.z, a0, acc0[10]); acc1[10] = fmaf(r2.z, a1, acc1[10]);
        acc0[11] = fmaf(r2.w, a0, acc0[11]); acc1[11] = fmaf(r2.w, a1, acc1[11]);
        acc0[12] = fmaf(r3.x, a0, acc0[12]); acc1[12] = fmaf(r3.x, a1, acc1[12]);
        acc0[13] = fmaf(r3.y, a0, acc0[13]); acc1[13] = fmaf(r3.y, a1, acc1[13]);
        acc0[14] = fmaf(r3.z, a0, acc0[14]); acc1[14] = fmaf(r3.z, a1, acc1[14]);
        acc0[15] = fmaf(r3.w, a0, acc0[15]); acc1[15] = fmaf(r3.w, a1, acc1[15]);
    }
    float s0 = 0.f, s1 = 0.f;
    #pragma unroll
    for (int d = 0; d < DDIM; d++) {
        float d0 = acc0[d] - ms[d * FF + f0];
        s0 = fmaf(d0, d0, s0);
        float d1 = acc1[d] - (v1 ? ms[d * FF + f1] : 0.f);
        s1 = fmaf(d1, d1, s1);
    }
    float per = sqrtf(s0 + 1e-8f) + (v1 ? sqrtf(s1 + 1e-8f) : 0.f);
    #pragma unroll
    for (int off = 16; off; off >>= 1)
        per += __shfl_xor_sync(FULLM, per, off);
    if (lane == 0)
        g_pooled[(size_t)b * NN + n] = per * (1.f / (float)FF);
}

// ---------------------------------------------------------------------------
// Final classifier: out[b][j] = sum_n pooled[b][n]*w_cls[n][j] + b_cls[j]
// ---------------------------------------------------------------------------
__global__ void __launch_bounds__(512) cls_kernel(
    const float* __restrict__ w_cls, const float* __restrict__ b_cls,
    float* __restrict__ out)
{
    __shared__ float ps[NN];
    const int tid = threadIdx.x;
    const int b = blockIdx.x;
    ps[tid] = g_pooled[(size_t)b * NN + tid];
    __syncthreads();
    if (tid < NCLS) {
        float a0 = 0.f, a1 = 0.f, a2 = 0.f, a3 = 0.f;
        #pragma unroll 4
        for (int n = 0; n < NN; n += 4) {
            a0 = fmaf(ps[n + 0], w_cls[(n + 0) * NCLS + tid], a0);
            a1 = fmaf(ps[n + 1], w_cls[(n + 1) * NCLS + tid], a1);
            a2 = fmaf(ps[n + 2], w_cls[(n + 2) * NCLS + tid], a2);
            a3 = fmaf(ps[n + 3], w_cls[(n + 3) * NCLS + tid], a3);
        }
        out[b * NCLS + tid] = (a0 + a1) + (a2 + a3) + b_cls[tid];
    }
}

extern "C" void kernel_launch(void* const* d_in, const int* in_sizes, int n_in,
                              void* d_out, int out_size)
{
    const float* x      = (const float*)d_in[0];  // [16,512,16,1]
    const float* w_fm1  = (const float*)d_in[1];  // [1,20]
    const float* w_mix1 = (const float*)d_in[2];  // [1,30]
    const float* w_fm2  = (const float*)d_in[3];  // [30,20]
    const float* w_mix2 = (const float*)d_in[4];  // [30,50]
    const float* m_last = (const float*)d_in[5];  // [16,50]
    const float* w_cls  = (const float*)d_in[6];  // [512,40]
    const float* b_cls  = (const float*)d_in[7];  // [40]
    float* out = (float*)d_out;                   // [16,40]

    constexpr size_t S1_SMEM = ((size_t)NN * STRIDE + KNN) * 4;                     // 41040
    constexpr size_t S2_SMEM = ((size_t)NN * STRIDE + KNN * FF + DDIM * FF
                               + CC * KNN) * 4;                                     // 50560

    cudaFuncSetAttribute(stage1_kernel, cudaFuncAttributeMaxDynamicSharedMemorySize, (int)S1_SMEM);
    cudaFuncSetAttribute(stage2_kernel, cudaFuncAttributeMaxDynamicSharedMemorySize, (int)S2_SMEM);

    dim3 grid(BPB, BB);   // 64 x 16 = 1024 blocks, 1 query per warp
    stage1_kernel<<<grid, NT, S1_SMEM>>>(x, w_fm1);
    stage2_kernel<<<grid, NT, S2_SMEM>>>(w_fm2, w_mix1, w_mix2, m_last);
    cls_kernel<<<BB, 512>>>(w_cls, b_cls, out);
}